// round 9
// baseline (speedup 1.0000x reference)
#include <cuda_runtime.h>
#include <cuda_fp16.h>
#include <stdint.h>
#include <math.h>

// ---------------- problem constants ----------------
#define CDIM    256
#define HDIM    56
#define WDIM    56
#define HW      3136
#define L_TOTAL 25088
#define DDIM    2304

// ---------------- scratch: single fp16 planes ----------------
__device__ __align__(128) __half g_t [(size_t)L_TOTAL * DDIM];
__device__ __align__(128) __half g_h [(size_t)L_TOTAL * CDIM];
__device__ __align__(128) __half g_p [(size_t)L_TOTAL * DDIM];
__device__ __align__(128) __half g_w1[(size_t)CDIM * DDIM];
__device__ __align__(128) __half g_w2[(size_t)DDIM * CDIM];
__device__ __align__(128) __half g_w3[(size_t)CDIM * DDIM];

// ---------------- helpers ----------------
__device__ __forceinline__ uint32_t smem_u32(const void* p) {
    uint32_t a;
    asm("{ .reg .u64 t; cvta.to.shared.u64 t, %1; cvt.u32.u64 %0, t; }" : "=r"(a) : "l"(p));
    return a;
}
__device__ __forceinline__ void ldm_x4(uint32_t* r, uint32_t addr) {
    asm volatile("ldmatrix.sync.aligned.m8n8.x4.shared.b16 {%0,%1,%2,%3}, [%4];"
        : "=r"(r[0]), "=r"(r[1]), "=r"(r[2]), "=r"(r[3]) : "r"(addr));
}
__device__ __forceinline__ void mma16816(float* d, const uint32_t* a, uint32_t b0, uint32_t b1) {
    asm volatile("mma.sync.aligned.m16n8k16.row.col.f32.f16.f16.f32 "
        "{%0,%1,%2,%3}, {%4,%5,%6,%7}, {%8,%9}, {%0,%1,%2,%3};"
        : "+f"(d[0]), "+f"(d[1]), "+f"(d[2]), "+f"(d[3])
        : "r"(a[0]), "r"(a[1]), "r"(a[2]), "r"(a[3]), "r"(b0), "r"(b1));
}
__device__ __forceinline__ void cp_async16(uint32_t dst, const void* src) {
    asm volatile("cp.async.cg.shared.global [%0], [%1], 16;" :: "r"(dst), "l"(src));
}
#define CP_COMMIT() asm volatile("cp.async.commit_group;" ::: "memory")
#define CP_WAIT2()  asm volatile("cp.async.wait_group 2;" ::: "memory")

// ---------------- K0: tiled unfold -> fp16 plane ----------------
// grid (4 c-chunks, 56 h, 8 b), 256 threads. smem tile of x: [64c][3hh][58ww padded].
__global__ __launch_bounds__(256) void unfold_tiled(const float* __restrict__ x,
    __half* __restrict__ t)
{
    __shared__ __half xs[64 * 3 * 58];
    const int chunk = blockIdx.x;    // 0..3
    const int h     = blockIdx.y;    // 0..55
    const int b     = blockIdx.z;    // 0..7
    const int c0    = chunk * 64;
    const int tid   = threadIdx.x;

    // zero pad columns (ww = -1, 56)
    for (int i = tid; i < 64 * 3; i += 256) {
        xs[i * 58 + 0]  = __float2half(0.f);
        xs[i * 58 + 57] = __float2half(0.f);
    }
    // load interior
    for (int i = tid; i < 64 * 3 * 56; i += 256) {
        int w = i % 56;
        int rest = i / 56;
        int hh = rest % 3;
        int c  = rest / 3;
        int gh = h + hh - 1;
        float v = 0.f;
        if (gh >= 0 && gh < HDIM)
            v = x[((size_t)(b * CDIM + c0 + c) * HDIM + gh) * WDIM + w];
        xs[(c * 3 + hh) * 58 + (w + 1)] = __float2half(v);
    }
    __syncthreads();

    // write: 56 l-values x 288 half2 pairs (576 d per chunk)
    const int lbase = b * HW + h * WDIM;
    for (int pid = tid; pid < 56 * 288; pid += 256) {
        int j = pid % 288;          // pair index within chunk
        int w = pid / 288;
        int e0 = 2 * j;
        __half v0, v1;
        {
            int e = e0;
            int c = e / 9, r = e - 9 * c;
            int di = r / 3, dj = r - 3 * di;
            v0 = xs[(c * 3 + di) * 58 + (w + dj)];
        }
        {
            int e = e0 + 1;
            int c = e / 9, r = e - 9 * c;
            int di = r / 3, dj = r - 3 * di;
            v1 = xs[(c * 3 + di) * 58 + (w + dj)];
        }
        __half2 o; o.x = v0; o.y = v1;
        *(__half2*)(t + (size_t)(lbase + w) * DDIM + chunk * 576 + e0) = o;
    }
}

// ---------------- weight transpose: W[K,N] -> fp16 [N,K] ----------------
__global__ __launch_bounds__(256) void wtrans_h(const float* __restrict__ W,
    __half* __restrict__ o, int K, int N)
{
    int t = blockIdx.x * 256 + threadIdx.x;
    int NP = N * (K / 2);
    if (t >= NP) return;
    int kp = t % (K / 2), n = t / (K / 2);
    int k0 = kp * 2;
    __half2 h2;
    h2.x = __float2half(W[(size_t)k0 * N + n]);
    h2.y = __float2half(W[(size_t)(k0 + 1) * N + n]);
    *(__half2*)(o + (size_t)n * K + k0) = h2;
}

// ---------------- pipelined fp16 mma.sync GEMM ----------------
// C = epi(A @ B^T + bias); A [M,K] fp16, B [N,K] fp16.
// BM=128, BN template (64 or 128), BK=32, 256 threads, 4-stage cp.async, 1 sync/iter.
// MODE 1: relu -> fp16   MODE 2: sigmoid * X -> fp16   MODE 3: fp32 + bias
#define NSTAGE 4

template<int MODE, int BN>
__global__ __launch_bounds__(256, 2) void gemm_mma(
    const __half* __restrict__ A, const __half* __restrict__ B,
    const float* __restrict__ bias,
    const __half* __restrict__ X,
    __half* __restrict__ Oh, float* __restrict__ Of,
    int M, int N, int Kd)
{
    constexpr int BSTAGE = 8192 + BN * 64;   // A plane + B plane bytes
    constexpr int PB = BN / 32;              // 16-row B groups per warp
    constexpr int TN = BN / 16;              // 8-col n-tiles per warp

    extern __shared__ __align__(128) char smem[];
    const uint32_t sb = smem_u32(smem);

    const int tid  = threadIdx.x;
    const int lane = tid & 31;
    const int wid  = tid >> 5;
    const int warp_m = wid & 3;
    const int warp_n = wid >> 2;
    const int m0 = blockIdx.y * 128;
    const int n0 = blockIdx.x * BN;

    const int lr = tid >> 2;          // 0..63
    const int lc = tid & 3;           // 16B chunk 0..3

    float acc[2][TN][4];
    #pragma unroll
    for (int a = 0; a < 2; a++)
        #pragma unroll
        for (int b = 0; b < TN; b++)
            #pragma unroll
            for (int c = 0; c < 4; c++) acc[a][b][c] = 0.f;

    // ldmatrix per-lane addressing (64B rows, chunk swizzle c ^ ((r>>1)&3))
    const int grp = lane >> 3, r8 = lane & 7;
    const int rowoff = ((grp & 1) << 3) + r8;
    const int cg = grp >> 1;
    int offA[2], swA[2], offB[PB], swB[PB];
    #pragma unroll
    for (int tm = 0; tm < 2; tm++) {
        int r = warp_m * 32 + tm * 16 + rowoff;
        offA[tm] = r * 64; swA[tm] = (r >> 1) & 3;
    }
    #pragma unroll
    for (int p = 0; p < PB; p++) {
        int r = warp_n * (BN / 2) + p * 16 + rowoff;
        offB[p] = r * 64; swB[p] = (r >> 1) & 3;
    }

    const int NIT = Kd >> 5;

    auto load_stage = [&](int st, int k0) {
        uint32_t stb = sb + st * BSTAGE;
        #pragma unroll
        for (int i = 0; i < 2; i++) {
            int r = (i << 6) + lr;
            uint32_t dst = stb + r * 64 + ((lc ^ ((r >> 1) & 3)) << 4);
            cp_async16(dst, (const char*)(A + (size_t)(m0 + r) * Kd + k0 + lc * 8));
        }
        #pragma unroll
        for (int i = 0; i < BN / 64; i++) {
            int r = (i << 6) + lr;
            uint32_t dst = stb + 8192 + r * 64 + ((lc ^ ((r >> 1) & 3)) << 4);
            cp_async16(dst, (const char*)(B + (size_t)(n0 + r) * Kd + k0 + lc * 8));
        }
    };

    // prologue: stages 0..NSTAGE-2
    #pragma unroll
    for (int s = 0; s < NSTAGE - 1; s++) {
        load_stage(s, s * 32);
        CP_COMMIT();
    }

    for (int it = 0; it < NIT; it++) {
        CP_WAIT2();            // wait_group NSTAGE-2: stage it ready
        __syncthreads();       // all warps done with stage it-1

        int ls = it + NSTAGE - 1;
        if (ls < NIT) load_stage(ls % NSTAGE, ls * 32);
        CP_COMMIT();

        const uint32_t stb = sb + (it % NSTAGE) * BSTAGE;
        #pragma unroll
        for (int ks = 0; ks < 2; ks++) {
            uint32_t ah[2][4], bh[PB][4];
            #pragma unroll
            for (int tm = 0; tm < 2; tm++) {
                uint32_t colA = (uint32_t)((((ks << 1) | cg) ^ swA[tm]) << 4);
                ldm_x4(ah[tm], stb + offA[tm] + colA);
            }
            #pragma unroll
            for (int p = 0; p < PB; p++) {
                uint32_t colB = (uint32_t)((((ks << 1) | cg) ^ swB[p]) << 4);
                ldm_x4(bh[p], stb + 8192 + offB[p] + colB);
            }
            #pragma unroll
            for (int tm = 0; tm < 2; tm++)
                #pragma unroll
                for (int tn = 0; tn < TN; tn++) {
                    int p = tn >> 1, o = tn & 1;
                    mma16816(acc[tm][tn], ah[tm], bh[p][o], bh[p][2 + o]);
                }
        }
    }

    // ---------------- epilogue ----------------
    const int qr = lane >> 2;
    const int qc = (lane & 3) * 2;
    #pragma unroll
    for (int tm = 0; tm < 2; tm++) {
        int mb = m0 + warp_m * 32 + tm * 16;
        #pragma unroll
        for (int tn = 0; tn < TN; tn++) {
            int n = n0 + warp_n * (BN / 2) + tn * 8 + qc;
            float bx = bias[n], by = bias[n + 1];
            #pragma unroll
            for (int half = 0; half < 2; half++) {
                int m = mb + qr + half * 8;
                float vx = acc[tm][tn][half * 2 + 0] + bx;
                float vy = acc[tm][tn][half * 2 + 1] + by;
                size_t o = (size_t)m * N + n;
                if (MODE == 1) {
                    __half2 w;
                    w.x = __float2half(fmaxf(vx, 0.f));
                    w.y = __float2half(fmaxf(vy, 0.f));
                    *(__half2*)(Oh + o) = w;
                } else if (MODE == 2) {
                    float sx = 1.f / (1.f + __expf(-vx));
                    float sy = 1.f / (1.f + __expf(-vy));
                    __half2 tv = *(const __half2*)(X + o);
                    __half2 w;
                    w.x = __float2half(__half2float(tv.x) * sx);
                    w.y = __float2half(__half2float(tv.y) * sy);
                    *(__half2*)(Oh + o) = w;
                } else {
                    float2 w; w.x = vx; w.y = vy;
                    *(float2*)(Of + o) = w;
                }
            }
        }
    }
}

// ---------------- host launch ----------------
extern "C" void kernel_launch(void* const* d_in, const int* in_sizes, int n_in,
                              void* d_out, int out_size)
{
    const float* x  = (const float*)d_in[0];
    const float* W1 = (const float*)d_in[1];
    const float* b1 = (const float*)d_in[2];
    const float* W2 = (const float*)d_in[3];
    const float* b2 = (const float*)d_in[4];
    const float* W3 = (const float*)d_in[5];
    const float* b3 = (const float*)d_in[6];
    float* out = (float*)d_out;

    __half *pt, *ph, *pp, *w1, *w2, *w3;
    cudaGetSymbolAddress((void**)&pt, g_t);
    cudaGetSymbolAddress((void**)&ph, g_h);
    cudaGetSymbolAddress((void**)&pp, g_p);
    cudaGetSymbolAddress((void**)&w1, g_w1);
    cudaGetSymbolAddress((void**)&w2, g_w2);
    cudaGetSymbolAddress((void**)&w3, g_w3);

    const int SM64  = NSTAGE * (8192 + 64 * 64);    // 49152
    const int SM128 = NSTAGE * (8192 + 128 * 64);   // 65536
    cudaFuncSetAttribute(gemm_mma<1, 64>,  cudaFuncAttributeMaxDynamicSharedMemorySize, SM64);
    cudaFuncSetAttribute(gemm_mma<2, 128>, cudaFuncAttributeMaxDynamicSharedMemorySize, SM128);
    cudaFuncSetAttribute(gemm_mma<3, 64>,  cudaFuncAttributeMaxDynamicSharedMemorySize, SM64);

    unfold_tiled<<<dim3(4, 56, 8), 256>>>(x, pt);
    wtrans_h<<<(CDIM * (DDIM / 2) + 255) / 256, 256>>>(W1, w1, DDIM, CDIM);
    wtrans_h<<<(DDIM * (CDIM / 2) + 255) / 256, 256>>>(W2, w2, CDIM, DDIM);
    wtrans_h<<<(CDIM * (DDIM / 2) + 255) / 256, 256>>>(W3, w3, DDIM, CDIM);

    // K1: h = relu(t @ W1 + b1)        [25088 x 256],  K=2304
    gemm_mma<1, 64><<<dim3(CDIM / 64, L_TOTAL / 128), 256, SM64>>>(
        pt, w1, b1, nullptr, ph, nullptr, L_TOTAL, CDIM, DDIM);
    // K2: p = t * sigmoid(h @ W2 + b2) [25088 x 2304], K=256
    gemm_mma<2, 128><<<dim3(DDIM / 128, L_TOTAL / 128), 256, SM128>>>(
        ph, w2, b2, pt, pp, nullptr, L_TOTAL, DDIM, CDIM);
    // K3: out = p @ W3 + b3            [25088 x 256],  K=2304
    gemm_mma<3, 64><<<dim3(CDIM / 64, L_TOTAL / 128), 256, SM64>>>(
        pp, w3, b3, nullptr, nullptr, out, L_TOTAL, CDIM, DDIM);
}